// round 13
// baseline (speedup 1.0000x reference)
#include <cuda_runtime.h>
#include <cuda_fp16.h>
#include <cstdint>

// B=1024, T=200, IN=H=128. rows = 204800.
__device__ __half g_xall16[(size_t)204800 * 384];   // [flat row][xu|xr|xg] fp16, biases folded
__device__ float g_logits[204800];
__device__ float g_att[204800];

__device__ __forceinline__ uint32_t smem_u32(const void* p) {
    return (uint32_t)__cvta_generic_to_shared(p);
}
__device__ __forceinline__ void ldmatrix_x4(uint32_t a[4], uint32_t addr) {
    asm volatile("ldmatrix.sync.aligned.m8n8.x4.shared.b16 {%0,%1,%2,%3}, [%4];"
                 : "=r"(a[0]), "=r"(a[1]), "=r"(a[2]), "=r"(a[3]) : "r"(addr));
}
__device__ __forceinline__ void ldmatrix_x4_trans(uint32_t a[4], uint32_t addr) {
    asm volatile("ldmatrix.sync.aligned.m8n8.x4.trans.shared.b16 {%0,%1,%2,%3}, [%4];"
                 : "=r"(a[0]), "=r"(a[1]), "=r"(a[2]), "=r"(a[3]) : "r"(addr));
}
__device__ __forceinline__ void mma16816(float c[4], const uint32_t a[4], uint32_t b0, uint32_t b1) {
    asm volatile("mma.sync.aligned.m16n8k16.row.col.f32.f16.f16.f32 "
                 "{%0,%1,%2,%3},{%4,%5,%6,%7},{%8,%9},{%0,%1,%2,%3};"
                 : "+f"(c[0]), "+f"(c[1]), "+f"(c[2]), "+f"(c[3])
                 : "r"(a[0]), "r"(a[1]), "r"(a[2]), "r"(a[3]), "r"(b0), "r"(b1));
}
__device__ __forceinline__ uint32_t f2h2(float x, float y) {
    __half2 h = __floats2half2_rn(x, y);
    return *reinterpret_cast<uint32_t*>(&h);
}
__device__ __forceinline__ float tanhapx(float x) {
    float y; asm("tanh.approx.f32 %0, %1;" : "=f"(y) : "f"(x)); return y;
}

// ================= K1: logits + x projections, register-resident weights (frozen) =================
#define K1_HS_OFF  17408
#define K1_SWB_OFF 34816
#define K1_LGP_OFF 50176
#define K1_SMEM    51200
#define K1_TILES   3200

__global__ __launch_bounds__(512) void k1_ff(
    const float* __restrict__ targets, const float* __restrict__ hist,
    const float* __restrict__ Ww,  const float* __restrict__ Wb,
    const float* __restrict__ xuw, const float* __restrict__ xub,
    const float* __restrict__ xrw, const float* __restrict__ xrb,
    const float* __restrict__ xgw, const float* __restrict__ xgb)
{
    extern __shared__ char sm[];
    __half* tg16 = (__half*)sm;
    __half* hs16 = (__half*)(sm + K1_HS_OFF);
    uint32_t* swb = (uint32_t*)(sm + K1_SWB_OFF);
    float* lgp = (float*)(sm + K1_LGP_OFF);

    const int t = threadIdx.x, w = t >> 5, lane = t & 31;
    const int q = lane & 3, l4 = lane >> 2;
    const int g = w >> 2;
    const int cb = 32 * (w & 3);
    const bool is_logit = (g == 0);

    const float* W  = (g == 0) ? Ww  : (g == 1) ? xuw : (g == 2) ? xrw : xgw;
    const float* Bv = (g == 0) ? Wb  : (g == 1) ? xub : (g == 2) ? xrb : xgb;

    uint32_t bfr[4][8][2];
    float2 bs[4];
    #pragma unroll
    for (int ct = 0; ct < 4; ct++) {
        const int n = cb + 8 * ct + l4;
        bs[ct] = *(const float2*)&Bv[cb + 8 * ct + 2 * q];
        #pragma unroll
        for (int kt = 0; kt < 8; kt++) {
            float2 wa = *(const float2*)&W[n * 128 + kt * 16 + 2 * q];
            float2 wb = *(const float2*)&W[n * 128 + kt * 16 + 2 * q + 8];
            bfr[ct][kt][0] = f2h2(wa.x, wa.y);
            bfr[ct][kt][1] = f2h2(wb.x, wb.y);
        }
    }

    const uint32_t abase = smem_u32(is_logit ? tg16 : hs16)
                         + (lane & 15) * 272 + (lane >> 4) * 16;
    uint32_t* swbw = swb + (w - 4) * 320;
    const int gc0 = (g - 1) * 128 + cb;

    for (int tile = blockIdx.x; tile < K1_TILES; tile += 148) {
        const size_t row0 = (size_t)tile * 64;
        __syncthreads();
        #pragma unroll
        for (int j = 0; j < 8; j++) {
            int idx = t + 512 * j;
            int r = idx >> 6, c2 = idx & 63;
            float2 tv = *(const float2*)&targets[(row0 + r) * 128 + 2 * c2];
            float2 hv = *(const float2*)&hist[(row0 + r) * 128 + 2 * c2];
            *(__half2*)&tg16[r * 136 + 2 * c2] = __floats2half2_rn(tv.x, tv.y);
            *(__half2*)&hs16[r * 136 + 2 * c2] = __floats2half2_rn(hv.x, hv.y);
        }
        __syncthreads();

        #pragma unroll
        for (int mt = 0; mt < 4; mt++) {
            float acc[4][4];
            #pragma unroll
            for (int ct = 0; ct < 4; ct++) {
                if (is_logit) {
                    acc[ct][0] = acc[ct][1] = acc[ct][2] = acc[ct][3] = 0.f;
                } else {
                    acc[ct][0] = bs[ct].x; acc[ct][1] = bs[ct].y;
                    acc[ct][2] = bs[ct].x; acc[ct][3] = bs[ct].y;
                }
            }
            const uint32_t ab = abase + mt * 4352;
            #pragma unroll
            for (int kc = 0; kc < 2; kc++) {
                uint32_t af[4][4];
                #pragma unroll
                for (int k4 = 0; k4 < 4; k4++)
                    ldmatrix_x4(af[k4], ab + (4 * kc + k4) * 32);
                #pragma unroll
                for (int ct = 0; ct < 4; ct++)
                    #pragma unroll
                    for (int k4 = 0; k4 < 4; k4++)
                        mma16816(acc[ct], af[k4], bfr[ct][4 * kc + k4][0], bfr[ct][4 * kc + k4][1]);
            }
            const int r0 = mt * 16 + l4, r1 = r0 + 8;
            if (is_logit) {
                float p0 = 0.f, p1 = 0.f;
                #pragma unroll
                for (int ct = 0; ct < 4; ct++) {
                    const int col = cb + 8 * ct + 2 * q;
                    float2 h0 = __half22float2(*(const __half2*)&hs16[r0 * 136 + col]);
                    float2 h1 = __half22float2(*(const __half2*)&hs16[r1 * 136 + col]);
                    p0 += (acc[ct][0] + bs[ct].x) * h0.x + (acc[ct][1] + bs[ct].y) * h0.y;
                    p1 += (acc[ct][2] + bs[ct].x) * h1.x + (acc[ct][3] + bs[ct].y) * h1.y;
                }
                p0 += __shfl_xor_sync(~0u, p0, 1); p0 += __shfl_xor_sync(~0u, p0, 2);
                p1 += __shfl_xor_sync(~0u, p1, 1); p1 += __shfl_xor_sync(~0u, p1, 2);
                if (q == 0) {
                    lgp[w * 64 + r0] = p0;
                    lgp[w * 64 + r1] = p1;
                }
            } else {
                #pragma unroll
                for (int ct = 0; ct < 4; ct++) {
                    swbw[l4 * 20 + ct * 4 + q]       = f2h2(acc[ct][0], acc[ct][1]);
                    swbw[(l4 + 8) * 20 + ct * 4 + q] = f2h2(acc[ct][2], acc[ct][3]);
                }
                __syncwarp();
                #pragma unroll
                for (int i = lane; i < 256; i += 32) {
                    int row = i >> 4, c = i & 15;
                    uint32_t v = swbw[row * 20 + c];
                    *(uint32_t*)&g_xall16[(row0 + mt * 16 + row) * 384 + gc0 + 2 * c] = v;
                }
                __syncwarp();
            }
        }
        __syncthreads();
        if (t < 64)
            g_logits[row0 + t] = lgp[t] + lgp[64 + t] + lgp[128 + t] + lgp[192 + t];
    }
}

// ================= K2: softmax over T (frozen) =================
__global__ void k2_softmax()
{
    __shared__ float red[256];
    const int b = blockIdx.x, t = threadIdx.x;
    float v = (t < 200) ? g_logits[b * 200 + t] : -1e30f;
    red[t] = v; __syncthreads();
    for (int s = 128; s; s >>= 1) { if (t < s) red[t] = fmaxf(red[t], red[t + s]); __syncthreads(); }
    float mx = red[0]; __syncthreads();
    float e = (t < 200) ? __expf(v - mx) : 0.f;
    red[t] = e; __syncthreads();
    for (int s = 128; s; s >>= 1) { if (t < s) red[t] += red[t + s]; __syncthreads(); }
    float inv = __fdividef(1.f, red[0]);
    if (t < 200) g_att[b * 200 + t] = e * inv;
}

// ================= K3: transposed GRU scan, 2 CTAs/SM (4 rows/CTA) + fused final linear =================
// 256 CTAs x 256 thr, __launch_bounds__(256,2). Batch rows 4 real + 4 zero-pad in n8.
// Gates u,r: register A-frags (64 regs). Gate g: smem A-frags via ldmatrix (saves 32 regs).
#define XPAD 196

__global__ __launch_bounds__(256, 2) void k3_scan(
    const float* __restrict__ targets,
    const float* __restrict__ huw, const float* __restrict__ hub,
    const float* __restrict__ hrw, const float* __restrict__ hrb,
    const float* __restrict__ hgw, const float* __restrict__ hgb,
    const float* __restrict__ lnw, const float* __restrict__ lnb,
    float* __restrict__ out)
{
    __shared__ __align__(16) __half wg2[128 * 136];     // gate-g weights, 34816 B
    __shared__ __align__(16) __half hT[2][128 * 8];     // 2 x 2048 B
    __shared__ __align__(16) uint32_t xbuf[2][8 * XPAD];
    __shared__ float attbuf[2][8];
    __shared__ __align__(16) float xs[4][260];
    const int t = threadIdx.x, w = t >> 5, lane = t & 31;
    const int q = lane & 3, l4 = lane >> 2;
    const size_t rowb = (size_t)blockIdx.x * 4;

    // ---- gates u,r: register A-fragments ----
    uint32_t afr[2][8][4];
    float bias_[3][2];
    #pragma unroll
    for (int g = 0; g < 2; g++) {
        const float* W  = (g == 0) ? huw : hrw;
        const float* Bv = (g == 0) ? hub : hrb;
        bias_[g][0] = Bv[16 * w + l4];
        bias_[g][1] = Bv[16 * w + l4 + 8];
        #pragma unroll
        for (int kt = 0; kt < 8; kt++) {
            const float* bp = W + (16 * w + l4) * 128 + kt * 16 + 2 * q;
            float2 v0 = *(const float2*)(bp);
            float2 v2 = *(const float2*)(bp + 8);
            float2 v1 = *(const float2*)(bp + 8 * 128);
            float2 v3 = *(const float2*)(bp + 8 * 128 + 8);
            afr[g][kt][0] = f2h2(v0.x, v0.y);
            afr[g][kt][1] = f2h2(v1.x, v1.y);
            afr[g][kt][2] = f2h2(v2.x, v2.y);
            afr[g][kt][3] = f2h2(v3.x, v3.y);
        }
    }
    bias_[2][0] = hgb[16 * w + l4];
    bias_[2][1] = hgb[16 * w + l4 + 8];

    // ---- gate g: stage weights fp16 in smem (row m, 272B stride, conflict-free) ----
    for (int i = t; i < 8192; i += 256) {               // float2 granules
        int r = i >> 6, c2 = i & 63;
        float2 v = *(const float2*)&hgw[r * 128 + c2 * 2];
        *(__half2*)&wg2[r * 136 + c2 * 2] = __floats2half2_rn(v.x, v.y);
    }

    // zero hT (both), xbuf pad rows 4-7 (both), attbuf (both)
    for (int i = t; i < 2048; i += 256) ((__half*)hT)[i] = __float2half(0.f);
    for (int i = t; i < 2 * 4 * XPAD; i += 256) {
        int b = i / (4 * XPAD), r = i % (4 * XPAD);
        xbuf[b][4 * XPAD + r] = 0u;
    }
    if (t < 16) attbuf[t >> 3][t & 7] = 0.f;

    // step-0 x/att into buffer 0 (rows 0-3, coalesced)
    for (int i = t; i < 768; i += 256) {
        int row = i / 192, col = i % 192;
        xbuf[0][row * XPAD + col] =
            *(const uint32_t*)&g_xall16[((rowb + row) * 200) * 384 + col * 2];
    }
    if (t < 4) attbuf[0][t] = g_att[(rowb + t) * 200];
    __syncthreads();

    float hm[4] = {0.f, 0.f, 0.f, 0.f};   // (col l4,b 2q),(l4,2q+1),(l4+8,2q),(l4+8,2q+1)
    const uint32_t hTb = smem_u32(hT) + lane * 16;
    const uint32_t g2b = smem_u32(wg2) + (16 * w + (lane & 15)) * 272 + (lane >> 4) * 16;
    const int colA = 16 * w + l4, colB = colA + 8;

    for (int step = 0; step < 200; step++) {
        const int rb = step & 1, wb = 1 - rb;

        // prefetch next step's x/att (distance 1)
        uint32_t xr3[3]; float attr = 0.f;
        if (step < 199) {
            #pragma unroll
            for (int j = 0; j < 3; j++) {
                int idx = t + j * 256;
                int row = idx / 192, col = idx % 192;
                xr3[j] = *(const uint32_t*)&g_xall16[((rowb + row) * 200 + step + 1) * 384 + col * 2];
            }
            if (t < 4) attr = g_att[(rowb + t) * 200 + step + 1];
        }

        // acc init from x (pad rows read zeros)
        const char* xb = (const char*)xbuf[rb];
        float acc[3][4], xg4[4];
        #pragma unroll
        for (int c = 0; c < 4; c++) {
            const int bofs = (2 * q + (c & 1)) * (XPAD * 4) + ((c >> 1) ? colB : colA) * 2;
            acc[0][c] = __half2float(*(const __half*)(xb + bofs));
            acc[1][c] = __half2float(*(const __half*)(xb + bofs + 256));
            xg4[c]    = __half2float(*(const __half*)(xb + bofs + 512));
            acc[2][c] = 0.f;
        }
        const float attv0 = attbuf[rb][2 * q], attv1 = attbuf[rb][2 * q + 1];

        // B-frags from hT (x4 trans, linear conflict-free)
        uint32_t bf[8][2];
        #pragma unroll
        for (int j = 0; j < 4; j++) {
            uint32_t r4[4];
            ldmatrix_x4_trans(r4, hTb + rb * 2048 + j * 512);
            bf[2 * j][0] = r4[0]; bf[2 * j][1] = r4[1];
            bf[2 * j + 1][0] = r4[2]; bf[2 * j + 1][1] = r4[3];
        }
        #pragma unroll
        for (int kt = 0; kt < 8; kt++) {
            uint32_t g2f[4];
            ldmatrix_x4(g2f, g2b + kt * 32);
            mma16816(acc[0], afr[0][kt], bf[kt][0], bf[kt][1]);
            mma16816(acc[1], afr[1][kt], bf[kt][0], bf[kt][1]);
            mma16816(acc[2], g2f,        bf[kt][0], bf[kt][1]);
        }

        float hn[4];
        #pragma unroll
        for (int c = 0; c < 4; c++) {
            const int hi = c >> 1;
            const float ae = (c & 1) ? attv1 : attv0;
            float u = fmaf(tanhapx(0.5f * (acc[0][c] + bias_[0][hi])), 0.5f, 0.5f) * ae;
            float r = fmaf(tanhapx(0.5f * (acc[1][c] + bias_[1][hi])), 0.5f, 0.5f);
            float pre = xg4[c] + r * (acc[2][c] + bias_[2][hi]);
            float gg = tanhapx(pre);
            hn[c] = fmaf(u, gg - hm[c], hm[c]);
        }
        // publish hT[wb] (pad batches store zeros — stays zero)
        *(uint32_t*)((char*)hT[wb] + colA * 16 + 4 * q) = f2h2(hn[0], hn[1]);
        *(uint32_t*)((char*)hT[wb] + colB * 16 + 4 * q) = f2h2(hn[2], hn[3]);
        hm[0] = hn[0]; hm[1] = hn[1]; hm[2] = hn[2]; hm[3] = hn[3];

        if (step < 199) {
            #pragma unroll
            for (int j = 0; j < 3; j++) {
                int idx = t + j * 256;
                int row = idx / 192, col = idx % 192;
                xbuf[wb][row * XPAD + col] = xr3[j];
            }
            if (t < 4) attbuf[wb][t] = attr;
        }
        __syncthreads();
    }

    // ---- fused final linear: out = [h, targets[:,0]] @ ln2_w^T + b (4 batches) ----
    if (q < 2) {
        xs[2 * q][colA]     = hm[0];
        xs[2 * q + 1][colA] = hm[1];
        xs[2 * q][colB]     = hm[2];
        xs[2 * q + 1][colB] = hm[3];
    }
    for (int i = t; i < 512; i += 256) {
        int bb = i >> 7, c = i & 127;
        xs[bb][128 + c] = targets[(size_t)(rowb + bb) * 200 * 128 + c];
    }
    __syncthreads();
    const int col = t & 127, grp = t >> 7;
    float acc2[2];
    const float bv = lnb[col];
    acc2[0] = bv; acc2[1] = bv;
    const float4* wr = (const float4*)(lnw + (size_t)col * 256);
    #pragma unroll 8
    for (int k = 0; k < 64; k++) {
        float4 wv = wr[k];
        #pragma unroll
        for (int i = 0; i < 2; i++) {
            float4 xv = *(const float4*)&xs[grp * 2 + i][k * 4];
            acc2[i] += wv.x * xv.x + wv.y * xv.y + wv.z * xv.z + wv.w * xv.w;
        }
    }
    #pragma unroll
    for (int i = 0; i < 2; i++)
        out[(rowb + grp * 2 + i) * 128 + col] = acc2[i];
}

extern "C" void kernel_launch(void* const* d_in, const int* in_sizes, int n_in,
                              void* d_out, int out_size)
{
    const float* targets = (const float*)d_in[0];
    const float* hist    = (const float*)d_in[1];
    const float* Ww  = (const float*)d_in[2];  const float* Wb  = (const float*)d_in[3];
    const float* xuw = (const float*)d_in[4];  const float* xub = (const float*)d_in[5];
    const float* huw = (const float*)d_in[6];  const float* hub = (const float*)d_in[7];
    const float* xrw = (const float*)d_in[8];  const float* xrb = (const float*)d_in[9];
    const float* hrw = (const float*)d_in[10]; const float* hrb = (const float*)d_in[11];
    const float* xgw = (const float*)d_in[12]; const float* xgb = (const float*)d_in[13];
    const float* hgw = (const float*)d_in[14]; const float* hgb = (const float*)d_in[15];
    const float* lnw = (const float*)d_in[16]; const float* lnb = (const float*)d_in[17];
    float* out = (float*)d_out;

    cudaFuncSetAttribute(k1_ff, cudaFuncAttributeMaxDynamicSharedMemorySize, K1_SMEM);

    k1_ff<<<148, 512, K1_SMEM>>>(targets, hist, Ww, Wb, xuw, xub, xrw, xrb, xgw, xgb);
    k2_softmax<<<1024, 256>>>();
    k3_scan<<<256, 256>>>(targets, huw, hub, hrw, hrb, hgw, hgb, lnw, lnb, out);
}

// round 14
// speedup vs baseline: 1.0857x; 1.0857x over previous
#include <cuda_runtime.h>
#include <cuda_fp16.h>
#include <cstdint>

// B=1024, T=200, IN=H=128. rows = 204800.
__device__ __half g_xall16[(size_t)204800 * 384];   // [flat row][xu|xr|xg] fp16, biases folded
__device__ float g_logits[204800];
__device__ float g_att[204800];

__device__ __forceinline__ uint32_t smem_u32(const void* p) {
    return (uint32_t)__cvta_generic_to_shared(p);
}
__device__ __forceinline__ void ldmatrix_x4(uint32_t a[4], uint32_t addr) {
    asm volatile("ldmatrix.sync.aligned.m8n8.x4.shared.b16 {%0,%1,%2,%3}, [%4];"
                 : "=r"(a[0]), "=r"(a[1]), "=r"(a[2]), "=r"(a[3]) : "r"(addr));
}
__device__ __forceinline__ void ldmatrix_x4_trans(uint32_t a[4], uint32_t addr) {
    asm volatile("ldmatrix.sync.aligned.m8n8.x4.trans.shared.b16 {%0,%1,%2,%3}, [%4];"
                 : "=r"(a[0]), "=r"(a[1]), "=r"(a[2]), "=r"(a[3]) : "r"(addr));
}
__device__ __forceinline__ void mma16816(float c[4], const uint32_t a[4], uint32_t b0, uint32_t b1) {
    asm volatile("mma.sync.aligned.m16n8k16.row.col.f32.f16.f16.f32 "
                 "{%0,%1,%2,%3},{%4,%5,%6,%7},{%8,%9},{%0,%1,%2,%3};"
                 : "+f"(c[0]), "+f"(c[1]), "+f"(c[2]), "+f"(c[3])
                 : "r"(a[0]), "r"(a[1]), "r"(a[2]), "r"(a[3]), "r"(b0), "r"(b1));
}
__device__ __forceinline__ uint32_t f2h2(float x, float y) {
    __half2 h = __floats2half2_rn(x, y);
    return *reinterpret_cast<uint32_t*>(&h);
}
__device__ __forceinline__ float tanhapx(float x) {
    float y; asm("tanh.approx.f32 %0, %1;" : "=f"(y) : "f"(x)); return y;
}
__device__ __forceinline__ void cp_async16(uint32_t dst, const void* src) {
    asm volatile("cp.async.cg.shared.global [%0], [%1], 16;" :: "r"(dst), "l"(src));
}
__device__ __forceinline__ void cp_commit() { asm volatile("cp.async.commit_group;"); }
__device__ __forceinline__ void cp_wait0()  { asm volatile("cp.async.wait_group 0;" ::: "memory"); }

// ================= K0: dummy (shifts ncu capture onto k3_scan) =================
__global__ void k0_dummy() {}

// ================= K1: logits + x projections, cp.async input pipeline =================
// grid 148 persistent, block 512 (16 warps). Register-resident weight B-frags.
// Per tile: raw fp32 inputs arrive via cp.async (issued during previous tile's compute),
// converted to fp16 smem, then mma. smem layout (bytes):
//   rawT 0 (32768) | rawH 32768 (32768) | tg16 65536 (17408) | hs16 82944 (17408)
//   swb 100352 (15360) | lgp 115712 (1024)  -> total 116736
#define K1_RAWH_OFF 32768
#define K1_TG_OFF   65536
#define K1_HS_OFF   82944
#define K1_SWB_OFF  100352
#define K1_LGP_OFF  115712
#define K1_SMEM     116736
#define K1_TILES    3200

__global__ __launch_bounds__(512) void k1_ff(
    const float* __restrict__ targets, const float* __restrict__ hist,
    const float* __restrict__ Ww,  const float* __restrict__ Wb,
    const float* __restrict__ xuw, const float* __restrict__ xub,
    const float* __restrict__ xrw, const float* __restrict__ xrb,
    const float* __restrict__ xgw, const float* __restrict__ xgb)
{
    extern __shared__ char sm[];
    float4* rawT = (float4*)sm;
    float4* rawH = (float4*)(sm + K1_RAWH_OFF);
    __half* tg16 = (__half*)(sm + K1_TG_OFF);
    __half* hs16 = (__half*)(sm + K1_HS_OFF);
    uint32_t* swb = (uint32_t*)(sm + K1_SWB_OFF);
    float* lgp = (float*)(sm + K1_LGP_OFF);

    const int t = threadIdx.x, w = t >> 5, lane = t & 31;
    const int q = lane & 3, l4 = lane >> 2;
    const int g = w >> 2;
    const int cb = 32 * (w & 3);
    const bool is_logit = (g == 0);

    const float* W  = (g == 0) ? Ww  : (g == 1) ? xuw : (g == 2) ? xrw : xgw;
    const float* Bv = (g == 0) ? Wb  : (g == 1) ? xub : (g == 2) ? xrb : xgb;

    uint32_t bfr[4][8][2];
    float2 bs[4];
    #pragma unroll
    for (int ct = 0; ct < 4; ct++) {
        const int n = cb + 8 * ct + l4;
        bs[ct] = *(const float2*)&Bv[cb + 8 * ct + 2 * q];
        #pragma unroll
        for (int kt = 0; kt < 8; kt++) {
            float2 wa = *(const float2*)&W[n * 128 + kt * 16 + 2 * q];
            float2 wb = *(const float2*)&W[n * 128 + kt * 16 + 2 * q + 8];
            bfr[ct][kt][0] = f2h2(wa.x, wa.y);
            bfr[ct][kt][1] = f2h2(wb.x, wb.y);
        }
    }

    const uint32_t rawTu = smem_u32(rawT), rawHu = smem_u32(rawH);
    const uint32_t abase = smem_u32(is_logit ? tg16 : hs16)
                         + (lane & 15) * 272 + (lane >> 4) * 16;
    uint32_t* swbw = swb + (w - 4) * 320;
    const int gc0 = (g - 1) * 128 + cb;

    // prologue: async-load first tile (contiguous 32KB per array)
    {
        const size_t base = (size_t)blockIdx.x * 64 * 128;
        #pragma unroll
        for (int j = 0; j < 4; j++) {
            int i = t + 512 * j;
            cp_async16(rawTu + 16 * i, &targets[base + 4 * i]);
            cp_async16(rawHu + 16 * i, &hist[base + 4 * i]);
        }
        cp_commit();
    }

    for (int tile = blockIdx.x; tile < K1_TILES; tile += 148) {
        const size_t row0 = (size_t)tile * 64;
        cp_wait0();
        __syncthreads();                 // raw tile ready; prev lgp consumed

        // convert raw fp32 -> fp16 tiles (conflict-free LDS.128 / STS.64)
        #pragma unroll
        for (int j = 0; j < 4; j++) {
            int i = t + 512 * j;
            int r = i >> 5, c = (i & 31) * 4;
            float4 v = rawT[i];
            uint2 p; p.x = f2h2(v.x, v.y); p.y = f2h2(v.z, v.w);
            *(uint2*)&tg16[r * 136 + c] = p;
            v = rawH[i];
            p.x = f2h2(v.x, v.y); p.y = f2h2(v.z, v.w);
            *(uint2*)&hs16[r * 136 + c] = p;
        }
        __syncthreads();                 // fp16 ready; raw free for reuse

        // issue cp.async for NEXT tile (overlaps with compute below)
        if (tile + 148 < K1_TILES) {
            const size_t nbase = (size_t)(tile + 148) * 64 * 128;
            #pragma unroll
            for (int j = 0; j < 4; j++) {
                int i = t + 512 * j;
                cp_async16(rawTu + 16 * i, &targets[nbase + 4 * i]);
                cp_async16(rawHu + 16 * i, &hist[nbase + 4 * i]);
            }
        }
        cp_commit();

        #pragma unroll
        for (int mt = 0; mt < 4; mt++) {
            float acc[4][4];
            #pragma unroll
            for (int ct = 0; ct < 4; ct++) {
                if (is_logit) {
                    acc[ct][0] = acc[ct][1] = acc[ct][2] = acc[ct][3] = 0.f;
                } else {
                    acc[ct][0] = bs[ct].x; acc[ct][1] = bs[ct].y;
                    acc[ct][2] = bs[ct].x; acc[ct][3] = bs[ct].y;
                }
            }
            const uint32_t ab = abase + mt * 4352;
            #pragma unroll
            for (int kc = 0; kc < 2; kc++) {
                uint32_t af[4][4];
                #pragma unroll
                for (int k4 = 0; k4 < 4; k4++)
                    ldmatrix_x4(af[k4], ab + (4 * kc + k4) * 32);
                #pragma unroll
                for (int ct = 0; ct < 4; ct++)
                    #pragma unroll
                    for (int k4 = 0; k4 < 4; k4++)
                        mma16816(acc[ct], af[k4], bfr[ct][4 * kc + k4][0], bfr[ct][4 * kc + k4][1]);
            }
            const int r0 = mt * 16 + l4, r1 = r0 + 8;
            if (is_logit) {
                float p0 = 0.f, p1 = 0.f;
                #pragma unroll
                for (int ct = 0; ct < 4; ct++) {
                    const int col = cb + 8 * ct + 2 * q;
                    float2 h0 = __half22float2(*(const __half2*)&hs16[r0 * 136 + col]);
                    float2 h1 = __half22float2(*(const __half2*)&hs16[r1 * 136 + col]);
                    p0 += (acc[ct][0] + bs[ct].x) * h0.x + (acc[ct][1] + bs[ct].y) * h0.y;
                    p1 += (acc[ct][2] + bs[ct].x) * h1.x + (acc[ct][3] + bs[ct].y) * h1.y;
                }
                p0 += __shfl_xor_sync(~0u, p0, 1); p0 += __shfl_xor_sync(~0u, p0, 2);
                p1 += __shfl_xor_sync(~0u, p1, 1); p1 += __shfl_xor_sync(~0u, p1, 2);
                if (q == 0) {
                    lgp[w * 64 + r0] = p0;
                    lgp[w * 64 + r1] = p1;
                }
            } else {
                #pragma unroll
                for (int ct = 0; ct < 4; ct++) {
                    swbw[l4 * 20 + ct * 4 + q]       = f2h2(acc[ct][0], acc[ct][1]);
                    swbw[(l4 + 8) * 20 + ct * 4 + q] = f2h2(acc[ct][2], acc[ct][3]);
                }
                __syncwarp();
                #pragma unroll
                for (int i = lane; i < 256; i += 32) {
                    int row = i >> 4, c = i & 15;
                    uint32_t v = swbw[row * 20 + c];
                    *(uint32_t*)&g_xall16[(row0 + mt * 16 + row) * 384 + gc0 + 2 * c] = v;
                }
                __syncwarp();
            }
        }
        __syncthreads();
        if (t < 64)
            g_logits[row0 + t] = lgp[t] + lgp[64 + t] + lgp[128 + t] + lgp[192 + t];
    }
}

// ================= K2: softmax over T (frozen) =================
__global__ void k2_softmax()
{
    __shared__ float red[256];
    const int b = blockIdx.x, t = threadIdx.x;
    float v = (t < 200) ? g_logits[b * 200 + t] : -1e30f;
    red[t] = v; __syncthreads();
    for (int s = 128; s; s >>= 1) { if (t < s) red[t] = fmaxf(red[t], red[t + s]); __syncthreads(); }
    float mx = red[0]; __syncthreads();
    float e = (t < 200) ? __expf(v - mx) : 0.f;
    red[t] = e; __syncthreads();
    for (int s = 128; s; s >>= 1) { if (t < s) red[t] += red[t + s]; __syncthreads(); }
    float inv = __fdividef(1.f, red[0]);
    if (t < 200) g_att[b * 200 + t] = e * inv;
}

// ================= K3: transposed GRU scan (R11 best config, reverted) =================
#define XPAD 196

__global__ __launch_bounds__(256) void k3_scan(
    const float* __restrict__ targets,
    const float* __restrict__ huw, const float* __restrict__ hub,
    const float* __restrict__ hrw, const float* __restrict__ hrb,
    const float* __restrict__ hgw, const float* __restrict__ hgb,
    const float* __restrict__ lnw, const float* __restrict__ lnb,
    float* __restrict__ out)
{
    __shared__ __align__(16) __half hT[2][128 * 8];
    __shared__ __align__(16) uint32_t xbuf[2][8 * XPAD];
    __shared__ float attbuf[2][8];
    __shared__ __align__(16) float xs[8][260];
    const int t = threadIdx.x, w = t >> 5, lane = t & 31;
    const int q = lane & 3, l4 = lane >> 2;
    const size_t rowb = (size_t)blockIdx.x * 8;

    uint32_t afr[3][8][4];
    float bias_[3][2];
    #pragma unroll
    for (int g = 0; g < 3; g++) {
        const float* W  = (g == 0) ? huw : (g == 1) ? hrw : hgw;
        const float* Bv = (g == 0) ? hub : (g == 1) ? hrb : hgb;
        bias_[g][0] = Bv[16 * w + l4];
        bias_[g][1] = Bv[16 * w + l4 + 8];
        #pragma unroll
        for (int kt = 0; kt < 8; kt++) {
            const float* bp = W + (16 * w + l4) * 128 + kt * 16 + 2 * q;
            float2 v0 = *(const float2*)(bp);
            float2 v2 = *(const float2*)(bp + 8);
            float2 v1 = *(const float2*)(bp + 8 * 128);
            float2 v3 = *(const float2*)(bp + 8 * 128 + 8);
            afr[g][kt][0] = f2h2(v0.x, v0.y);
            afr[g][kt][1] = f2h2(v1.x, v1.y);
            afr[g][kt][2] = f2h2(v2.x, v2.y);
            afr[g][kt][3] = f2h2(v3.x, v3.y);
        }
    }
    for (int i = t; i < 2048; i += 256) ((__half*)hT)[i] = __float2half(0.f);

    for (int i = t; i < 1536; i += 256) {
        int row = i / 192, col = i % 192;
        xbuf[0][row * XPAD + col] =
            *(const uint32_t*)&g_xall16[((rowb + row) * 200) * 384 + col * 2];
    }
    if (t < 8) attbuf[0][t] = g_att[(rowb + t) * 200];
    __syncthreads();

    float hm[4] = {0.f, 0.f, 0.f, 0.f};
    const uint32_t hTb = smem_u32(hT) + lane * 16;
    const int colA = 16 * w + l4, colB = colA + 8;

    for (int step = 0; step < 200; step++) {
        const int rb = step & 1, wb = 1 - rb;

        uint32_t xr6[6]; float attr = 0.f;
        if (step < 199) {
            #pragma unroll
            for (int j = 0; j < 6; j++) {
                int idx = t + j * 256;
                int row = idx / 192, col = idx % 192;
                xr6[j] = *(const uint32_t*)&g_xall16[((rowb + row) * 200 + step + 1) * 384 + col * 2];
            }
            if (t < 8) attr = g_att[(rowb + t) * 200 + step + 1];
        }

        const char* xb = (const char*)xbuf[rb];
        float acc[3][4], xg4[4];
        #pragma unroll
        for (int c = 0; c < 4; c++) {
            const int bofs = (2 * q + (c & 1)) * (XPAD * 4) + ((c >> 1) ? colB : colA) * 2;
            acc[0][c] = __half2float(*(const __half*)(xb + bofs));
            acc[1][c] = __half2float(*(const __half*)(xb + bofs + 256));
            xg4[c]    = __half2float(*(const __half*)(xb + bofs + 512));
            acc[2][c] = 0.f;
        }
        const float attv0 = attbuf[rb][2 * q], attv1 = attbuf[rb][2 * q + 1];

        uint32_t bf[8][2];
        #pragma unroll
        for (int j = 0; j < 4; j++) {
            uint32_t r4[4];
            ldmatrix_x4_trans(r4, hTb + rb * 2048 + j * 512);
            bf[2 * j][0] = r4[0]; bf[2 * j][1] = r4[1];
            bf[2 * j + 1][0] = r4[2]; bf[2 * j + 1][1] = r4[3];
        }
        #pragma unroll
        for (int kt = 0; kt < 8; kt++) {
            mma16816(acc[0], afr[0][kt], bf[kt][0], bf[kt][1]);
            mma16816(acc[1], afr[1][kt], bf[kt][0], bf[kt][1]);
            mma16816(acc[2], afr[2][kt], bf[kt][0], bf[kt][1]);
        }

        float hn[4];
        #pragma unroll
        for (int c = 0; c < 4; c++) {
            const int hi = c >> 1;
            const float ae = (c & 1) ? attv1 : attv0;
            float u = fmaf(tanhapx(0.5f * (acc[0][c] + bias_[0][hi])), 0.5f, 0.5f) * ae;
            float r = fmaf(tanhapx(0.5f * (acc[1][c] + bias_[1][hi])), 0.5f, 0.5f);
            float pre = xg4[c] + r * (acc[2][c] + bias_[2][hi]);
            float gg = tanhapx(pre);
            hn[c] = fmaf(u, gg - hm[c], hm[c]);
        }
        *(uint32_t*)((char*)hT[wb] + colA * 16 + 4 * q) = f2h2(hn[0], hn[1]);
        *(uint32_t*)((char*)hT[wb] + colB * 16 + 4 * q) = f2h2(hn[2], hn[3]);
        hm[0] = hn[0]; hm[1] = hn[1]; hm[2] = hn[2]; hm[3] = hn[3];

        if (step < 199) {
            #pragma unroll
            for (int j = 0; j < 6; j++) {
                int idx = t + j * 256;
                int row = idx / 192, col = idx % 192;
                xbuf[wb][row * XPAD + col] = xr6[j];
            }
            if (t < 8) attbuf[wb][t] = attr;
        }
        __syncthreads();
    }

    // ---- fused final linear: out = [h, targets[:,0]] @ ln2_w^T + b ----
    xs[2 * q][colA]     = hm[0];
    xs[2 * q + 1][colA] = hm[1];
    xs[2 * q][colB]     = hm[2];
    xs[2 * q + 1][colB] = hm[3];
    for (int i = t; i < 1024; i += 256) {
        int bb = i >> 7, c = i & 127;
        xs[bb][128 + c] = targets[(size_t)(rowb + bb) * 200 * 128 + c];
    }
    __syncthreads();
    const int col = t & 127, grp = t >> 7;
    float acc4[4];
    const float bv = lnb[col];
    #pragma unroll
    for (int i = 0; i < 4; i++) acc4[i] = bv;
    const float4* wr = (const float4*)(lnw + (size_t)col * 256);
    #pragma unroll 4
    for (int k = 0; k < 64; k++) {
        float4 wv = wr[k];
        #pragma unroll
        for (int i = 0; i < 4; i++) {
            float4 xv = *(const float4*)&xs[grp * 4 + i][k * 4];
            acc4[i] += wv.x * xv.x + wv.y * xv.y + wv.z * xv.z + wv.w * xv.w;
        }
    }
    #pragma unroll
    for (int i = 0; i < 4; i++)
        out[(rowb + grp * 4 + i) * 128 + col] = acc4[i];
}

extern "C" void kernel_launch(void* const* d_in, const int* in_sizes, int n_in,
                              void* d_out, int out_size)
{
    const float* targets = (const float*)d_in[0];
    const float* hist    = (const float*)d_in[1];
    const float* Ww  = (const float*)d_in[2];  const float* Wb  = (const float*)d_in[3];
    const float* xuw = (const float*)d_in[4];  const float* xub = (const float*)d_in[5];
    const float* huw = (const float*)d_in[6];  const float* hub = (const float*)d_in[7];
    const float* xrw = (const float*)d_in[8];  const float* xrb = (const float*)d_in[9];
    const float* hrw = (const float*)d_in[10]; const float* hrb = (const float*)d_in[11];
    const float* xgw = (const float*)d_in[12]; const float* xgb = (const float*)d_in[13];
    const float* hgw = (const float*)d_in[14]; const float* hgb = (const float*)d_in[15];
    const float* lnw = (const float*)d_in[16]; const float* lnb = (const float*)d_in[17];
    float* out = (float*)d_out;

    cudaFuncSetAttribute(k1_ff, cudaFuncAttributeMaxDynamicSharedMemorySize, K1_SMEM);

    k0_dummy<<<1, 32>>>();
    k1_ff<<<148, 512, K1_SMEM>>>(targets, hist, Ww, Wb, xuw, xub, xrw, xrb, xgw, xgb);
    k2_softmax<<<1024, 256>>>();
    k3_scan<<<128, 256>>>(targets, huw, hub, hrw, hrb, hgw, hgb, lnw, lnb, out);
}

// round 15
// speedup vs baseline: 1.1060x; 1.0187x over previous
#include <cuda_runtime.h>
#include <cuda_fp16.h>
#include <cstdint>

// B=1024, T=200, IN=H=128. rows = 204800.
__device__ __half g_xall16[(size_t)204800 * 384];   // [flat row][xu|xr|xg] fp16, biases folded
__device__ float g_logits[204800];
__device__ float g_att[204800];

__device__ __forceinline__ uint32_t smem_u32(const void* p) {
    return (uint32_t)__cvta_generic_to_shared(p);
}
__device__ __forceinline__ void ldmatrix_x4(uint32_t a[4], uint32_t addr) {
    asm volatile("ldmatrix.sync.aligned.m8n8.x4.shared.b16 {%0,%1,%2,%3}, [%4];"
                 : "=r"(a[0]), "=r"(a[1]), "=r"(a[2]), "=r"(a[3]) : "r"(addr));
}
__device__ __forceinline__ void ldmatrix_x4_trans(uint32_t a[4], uint32_t addr) {
    asm volatile("ldmatrix.sync.aligned.m8n8.x4.trans.shared.b16 {%0,%1,%2,%3}, [%4];"
                 : "=r"(a[0]), "=r"(a[1]), "=r"(a[2]), "=r"(a[3]) : "r"(addr));
}
__device__ __forceinline__ void mma16816(float c[4], const uint32_t a[4], uint32_t b0, uint32_t b1) {
    asm volatile("mma.sync.aligned.m16n8k16.row.col.f32.f16.f16.f32 "
                 "{%0,%1,%2,%3},{%4,%5,%6,%7},{%8,%9},{%0,%1,%2,%3};"
                 : "+f"(c[0]), "+f"(c[1]), "+f"(c[2]), "+f"(c[3])
                 : "r"(a[0]), "r"(a[1]), "r"(a[2]), "r"(a[3]), "r"(b0), "r"(b1));
}
__device__ __forceinline__ uint32_t f2h2(float x, float y) {
    __half2 h = __floats2half2_rn(x, y);
    return *reinterpret_cast<uint32_t*>(&h);
}
__device__ __forceinline__ float tanhapx(float x) {
    float y; asm("tanh.approx.f32 %0, %1;" : "=f"(y) : "f"(x)); return y;
}
__device__ __forceinline__ void cp_async16(uint32_t dst, const void* src) {
    asm volatile("cp.async.cg.shared.global [%0], [%1], 16;" :: "r"(dst), "l"(src));
}
__device__ __forceinline__ void cp_commit() { asm volatile("cp.async.commit_group;"); }
__device__ __forceinline__ void cp_wait0()  { asm volatile("cp.async.wait_group 0;" ::: "memory"); }

// ================= K0: dummy (keeps ncu capture on k3_scan) =================
__global__ void k0_dummy() {}

// ================= K1: logits + x projections, cp.async input pipeline (frozen) =================
#define K1_RAWH_OFF 32768
#define K1_TG_OFF   65536
#define K1_HS_OFF   82944
#define K1_SWB_OFF  100352
#define K1_LGP_OFF  115712
#define K1_SMEM     116736
#define K1_TILES    3200

__global__ __launch_bounds__(512) void k1_ff(
    const float* __restrict__ targets, const float* __restrict__ hist,
    const float* __restrict__ Ww,  const float* __restrict__ Wb,
    const float* __restrict__ xuw, const float* __restrict__ xub,
    const float* __restrict__ xrw, const float* __restrict__ xrb,
    const float* __restrict__ xgw, const float* __restrict__ xgb)
{
    extern __shared__ char sm[];
    float4* rawT = (float4*)sm;
    float4* rawH = (float4*)(sm + K1_RAWH_OFF);
    __half* tg16 = (__half*)(sm + K1_TG_OFF);
    __half* hs16 = (__half*)(sm + K1_HS_OFF);
    uint32_t* swb = (uint32_t*)(sm + K1_SWB_OFF);
    float* lgp = (float*)(sm + K1_LGP_OFF);

    const int t = threadIdx.x, w = t >> 5, lane = t & 31;
    const int q = lane & 3, l4 = lane >> 2;
    const int g = w >> 2;
    const int cb = 32 * (w & 3);
    const bool is_logit = (g == 0);

    const float* W  = (g == 0) ? Ww  : (g == 1) ? xuw : (g == 2) ? xrw : xgw;
    const float* Bv = (g == 0) ? Wb  : (g == 1) ? xub : (g == 2) ? xrb : xgb;

    uint32_t bfr[4][8][2];
    float2 bs[4];
    #pragma unroll
    for (int ct = 0; ct < 4; ct++) {
        const int n = cb + 8 * ct + l4;
        bs[ct] = *(const float2*)&Bv[cb + 8 * ct + 2 * q];
        #pragma unroll
        for (int kt = 0; kt < 8; kt++) {
            float2 wa = *(const float2*)&W[n * 128 + kt * 16 + 2 * q];
            float2 wb = *(const float2*)&W[n * 128 + kt * 16 + 2 * q + 8];
            bfr[ct][kt][0] = f2h2(wa.x, wa.y);
            bfr[ct][kt][1] = f2h2(wb.x, wb.y);
        }
    }

    const uint32_t rawTu = smem_u32(rawT), rawHu = smem_u32(rawH);
    const uint32_t abase = smem_u32(is_logit ? tg16 : hs16)
                         + (lane & 15) * 272 + (lane >> 4) * 16;
    uint32_t* swbw = swb + (w - 4) * 320;
    const int gc0 = (g - 1) * 128 + cb;

    {
        const size_t base = (size_t)blockIdx.x * 64 * 128;
        #pragma unroll
        for (int j = 0; j < 4; j++) {
            int i = t + 512 * j;
            cp_async16(rawTu + 16 * i, &targets[base + 4 * i]);
            cp_async16(rawHu + 16 * i, &hist[base + 4 * i]);
        }
        cp_commit();
    }

    for (int tile = blockIdx.x; tile < K1_TILES; tile += 148) {
        const size_t row0 = (size_t)tile * 64;
        cp_wait0();
        __syncthreads();

        #pragma unroll
        for (int j = 0; j < 4; j++) {
            int i = t + 512 * j;
            int r = i >> 5, c = (i & 31) * 4;
            float4 v = rawT[i];
            uint2 p; p.x = f2h2(v.x, v.y); p.y = f2h2(v.z, v.w);
            *(uint2*)&tg16[r * 136 + c] = p;
            v = rawH[i];
            p.x = f2h2(v.x, v.y); p.y = f2h2(v.z, v.w);
            *(uint2*)&hs16[r * 136 + c] = p;
        }
        __syncthreads();

        if (tile + 148 < K1_TILES) {
            const size_t nbase = (size_t)(tile + 148) * 64 * 128;
            #pragma unroll
            for (int j = 0; j < 4; j++) {
                int i = t + 512 * j;
                cp_async16(rawTu + 16 * i, &targets[nbase + 4 * i]);
                cp_async16(rawHu + 16 * i, &hist[nbase + 4 * i]);
            }
        }
        cp_commit();

        #pragma unroll
        for (int mt = 0; mt < 4; mt++) {
            float acc[4][4];
            #pragma unroll
            for (int ct = 0; ct < 4; ct++) {
                if (is_logit) {
                    acc[ct][0] = acc[ct][1] = acc[ct][2] = acc[ct][3] = 0.f;
                } else {
                    acc[ct][0] = bs[ct].x; acc[ct][1] = bs[ct].y;
                    acc[ct][2] = bs[ct].x; acc[ct][3] = bs[ct].y;
                }
            }
            const uint32_t ab = abase + mt * 4352;
            #pragma unroll
            for (int kc = 0; kc < 2; kc++) {
                uint32_t af[4][4];
                #pragma unroll
                for (int k4 = 0; k4 < 4; k4++)
                    ldmatrix_x4(af[k4], ab + (4 * kc + k4) * 32);
                #pragma unroll
                for (int ct = 0; ct < 4; ct++)
                    #pragma unroll
                    for (int k4 = 0; k4 < 4; k4++)
                        mma16816(acc[ct], af[k4], bfr[ct][4 * kc + k4][0], bfr[ct][4 * kc + k4][1]);
            }
            const int r0 = mt * 16 + l4, r1 = r0 + 8;
            if (is_logit) {
                float p0 = 0.f, p1 = 0.f;
                #pragma unroll
                for (int ct = 0; ct < 4; ct++) {
                    const int col = cb + 8 * ct + 2 * q;
                    float2 h0 = __half22float2(*(const __half2*)&hs16[r0 * 136 + col]);
                    float2 h1 = __half22float2(*(const __half2*)&hs16[r1 * 136 + col]);
                    p0 += (acc[ct][0] + bs[ct].x) * h0.x + (acc[ct][1] + bs[ct].y) * h0.y;
                    p1 += (acc[ct][2] + bs[ct].x) * h1.x + (acc[ct][3] + bs[ct].y) * h1.y;
                }
                p0 += __shfl_xor_sync(~0u, p0, 1); p0 += __shfl_xor_sync(~0u, p0, 2);
                p1 += __shfl_xor_sync(~0u, p1, 1); p1 += __shfl_xor_sync(~0u, p1, 2);
                if (q == 0) {
                    lgp[w * 64 + r0] = p0;
                    lgp[w * 64 + r1] = p1;
                }
            } else {
                #pragma unroll
                for (int ct = 0; ct < 4; ct++) {
                    swbw[l4 * 20 + ct * 4 + q]       = f2h2(acc[ct][0], acc[ct][1]);
                    swbw[(l4 + 8) * 20 + ct * 4 + q] = f2h2(acc[ct][2], acc[ct][3]);
                }
                __syncwarp();
                #pragma unroll
                for (int i = lane; i < 256; i += 32) {
                    int row = i >> 4, c = i & 15;
                    uint32_t v = swbw[row * 20 + c];
                    *(uint32_t*)&g_xall16[(row0 + mt * 16 + row) * 384 + gc0 + 2 * c] = v;
                }
                __syncwarp();
            }
        }
        __syncthreads();
        if (t < 64)
            g_logits[row0 + t] = lgp[t] + lgp[64 + t] + lgp[128 + t] + lgp[192 + t];
    }
}

// ================= K2: softmax over T (frozen) =================
__global__ void k2_softmax()
{
    __shared__ float red[256];
    const int b = blockIdx.x, t = threadIdx.x;
    float v = (t < 200) ? g_logits[b * 200 + t] : -1e30f;
    red[t] = v; __syncthreads();
    for (int s = 128; s; s >>= 1) { if (t < s) red[t] = fmaxf(red[t], red[t + s]); __syncthreads(); }
    float mx = red[0]; __syncthreads();
    float e = (t < 200) ? __expf(v - mx) : 0.f;
    red[t] = e; __syncthreads();
    for (int s = 128; s; s >>= 1) { if (t < s) red[t] += red[t + s]; __syncthreads(); }
    float inv = __fdividef(1.f, red[0]);
    if (t < 200) g_att[b * 200 + t] = e * inv;
}

// ================= K3: transposed GRU scan — chain-shortened =================
// Changes vs R13: zero-init accumulators (x folded in epilogue, mma starts at LDSM),
// split accumulators (dep chain 8 -> 4, 6 interleaved chains), attall preloaded,
// pointer-strength-reduced prefetch.
#define XPAD 196

__global__ __launch_bounds__(256) void k3_scan(
    const float* __restrict__ targets,
    const float* __restrict__ huw, const float* __restrict__ hub,
    const float* __restrict__ hrw, const float* __restrict__ hrb,
    const float* __restrict__ hgw, const float* __restrict__ hgb,
    const float* __restrict__ lnw, const float* __restrict__ lnb,
    float* __restrict__ out)
{
    __shared__ __align__(16) __half hT[2][128 * 8];
    __shared__ __align__(16) uint32_t xbuf[2][8 * XPAD];
    __shared__ __align__(16) float attall[8][200];
    __shared__ __align__(16) float xs[8][260];
    const int t = threadIdx.x, w = t >> 5, lane = t & 31;
    const int q = lane & 3, l4 = lane >> 2;
    const size_t rowb = (size_t)blockIdx.x * 8;

    uint32_t afr[3][8][4];
    float bias_[3][2];
    #pragma unroll
    for (int g = 0; g < 3; g++) {
        const float* W  = (g == 0) ? huw : (g == 1) ? hrw : hgw;
        const float* Bv = (g == 0) ? hub : (g == 1) ? hrb : hgb;
        bias_[g][0] = Bv[16 * w + l4];
        bias_[g][1] = Bv[16 * w + l4 + 8];
        #pragma unroll
        for (int kt = 0; kt < 8; kt++) {
            const float* bp = W + (16 * w + l4) * 128 + kt * 16 + 2 * q;
            float2 v0 = *(const float2*)(bp);
            float2 v2 = *(const float2*)(bp + 8);
            float2 v1 = *(const float2*)(bp + 8 * 128);
            float2 v3 = *(const float2*)(bp + 8 * 128 + 8);
            afr[g][kt][0] = f2h2(v0.x, v0.y);
            afr[g][kt][1] = f2h2(v1.x, v1.y);
            afr[g][kt][2] = f2h2(v2.x, v2.y);
            afr[g][kt][3] = f2h2(v3.x, v3.y);
        }
    }
    for (int i = t; i < 2048; i += 256) ((__half*)hT)[i] = __float2half(0.f);

    // preload ALL att (once) + step-0 x
    for (int i = t; i < 1600; i += 256) {
        int row = i / 200, s = i % 200;
        attall[row][s] = g_att[(rowb + row) * 200 + s];
    }
    {
        const int row = t / 192 > 7 ? 7 : t / 192, col = t % 192;   // 1536 slots, 256 thr x 6
    }
    for (int i = t; i < 1536; i += 256) {
        int row = i / 192, col = i % 192;
        xbuf[0][row * XPAD + col] =
            *(const uint32_t*)&g_xall16[((rowb + row) * 200) * 384 + col * 2];
    }
    // per-thread strength-reduced prefetch pointers (6 slots), start at step 1
    const char* pf[6];
    #pragma unroll
    for (int j = 0; j < 6; j++) {
        int idx = t + j * 256;
        int row = idx / 192, col = idx % 192;
        pf[j] = (const char*)&g_xall16[((rowb + row) * 200 + 1) * 384 + col * 2];
    }
    __syncthreads();

    float hm[4] = {0.f, 0.f, 0.f, 0.f};
    const uint32_t hTb = smem_u32(hT) + lane * 16;
    const int colA = 16 * w + l4, colB = colA + 8;

    for (int step = 0; step < 200; step++) {
        const int rb = step & 1, wb = 1 - rb;

        // prefetch next step's x (LDG off chain; ptr += 768B per step)
        uint32_t xr6[6];
        if (step < 199) {
            #pragma unroll
            for (int j = 0; j < 6; j++) {
                xr6[j] = *(const uint32_t*)pf[j];
                pf[j] += 768;
            }
        }

        // B-frags from hT — chain head (no LDS dependency before mma now)
        uint32_t bf[8][2];
        #pragma unroll
        for (int j = 0; j < 4; j++) {
            uint32_t r4[4];
            ldmatrix_x4_trans(r4, hTb + rb * 2048 + j * 512);
            bf[2 * j][0] = r4[0]; bf[2 * j][1] = r4[1];
            bf[2 * j + 1][0] = r4[2]; bf[2 * j + 1][1] = r4[3];
        }
        // 6 interleaved mma chains, depth 4 each, zero-init
        float aA[3][4] = {{0,0,0,0},{0,0,0,0},{0,0,0,0}};
        float aB[3][4] = {{0,0,0,0},{0,0,0,0},{0,0,0,0}};
        #pragma unroll
        for (int k4 = 0; k4 < 4; k4++) {
            mma16816(aA[0], afr[0][k4],     bf[k4][0],     bf[k4][1]);
            mma16816(aB[0], afr[0][k4 + 4], bf[k4 + 4][0], bf[k4 + 4][1]);
            mma16816(aA[1], afr[1][k4],     bf[k4][0],     bf[k4][1]);
            mma16816(aB[1], afr[1][k4 + 4], bf[k4 + 4][0], bf[k4 + 4][1]);
            mma16816(aA[2], afr[2][k4],     bf[k4][0],     bf[k4][1]);
            mma16816(aB[2], afr[2][k4 + 4], bf[k4 + 4][0], bf[k4 + 4][1]);
        }

        // x-gather from smem (overlaps mma — independent)
        const char* xb = (const char*)xbuf[rb];
        float xu4[4], xr4[4], xg4[4];
        #pragma unroll
        for (int c = 0; c < 4; c++) {
            const int bofs = (2 * q + (c & 1)) * (XPAD * 4) + ((c >> 1) ? colB : colA) * 2;
            xu4[c] = __half2float(*(const __half*)(xb + bofs));
            xr4[c] = __half2float(*(const __half*)(xb + bofs + 256));
            xg4[c] = __half2float(*(const __half*)(xb + bofs + 512));
        }
        const float attv0 = attall[2 * q][step], attv1 = attall[2 * q + 1][step];

        float hn[4];
        #pragma unroll
        for (int c = 0; c < 4; c++) {
            const int hi = c >> 1;
            const float ae = (c & 1) ? attv1 : attv0;
            float su = aA[0][c] + aB[0][c] + xu4[c] + bias_[0][hi];
            float sr = aA[1][c] + aB[1][c] + xr4[c] + bias_[1][hi];
            float sg = aA[2][c] + aB[2][c] + bias_[2][hi];
            float u = fmaf(tanhapx(0.5f * su), 0.5f, 0.5f) * ae;
            float r = fmaf(tanhapx(0.5f * sr), 0.5f, 0.5f);
            float gg = tanhapx(fmaf(r, sg, xg4[c]));
            hn[c] = fmaf(u, gg - hm[c], hm[c]);
        }
        *(uint32_t*)((char*)hT[wb] + colA * 16 + 4 * q) = f2h2(hn[0], hn[1]);
        *(uint32_t*)((char*)hT[wb] + colB * 16 + 4 * q) = f2h2(hn[2], hn[3]);
        hm[0] = hn[0]; hm[1] = hn[1]; hm[2] = hn[2]; hm[3] = hn[3];

        if (step < 199) {
            #pragma unroll
            for (int j = 0; j < 6; j++) {
                int idx = t + j * 256;
                int row = idx / 192, col = idx % 192;
                xbuf[wb][row * XPAD + col] = xr6[j];
            }
        }
        __syncthreads();
    }

    // ---- fused final linear: out = [h, targets[:,0]] @ ln2_w^T + b ----
    xs[2 * q][colA]     = hm[0];
    xs[2 * q + 1][colA] = hm[1];
    xs[2 * q][colB]     = hm[2];
    xs[2 * q + 1][colB] = hm[3];
    for (int i = t; i < 1024; i += 256) {
        int bb = i >> 7, c = i & 127;
        xs[bb][128 + c] = targets[(size_t)(rowb + bb) * 200 * 128 + c];
    }
    __syncthreads();
    const int col = t & 127, grp = t >> 7;
    float acc4[4];
    const float bv = lnb[col];
    #pragma unroll
    for (int i = 0; i < 4; i++) acc4[i] = bv;
    const float4* wr = (const float4*)(lnw + (size_t)col * 256);
    #pragma unroll 4
    for (int k = 0; k < 64; k++) {
        float4 wv = wr[k];
        #pragma unroll
        for (int i = 0; i < 4; i++) {
            float4 xv = *(const float4*)&xs[grp * 4 + i][k * 4];
            acc4[i] += wv.x * xv.x + wv.y * xv.y + wv.z * xv.z + wv.w * xv.w;
        }
    }
    #pragma unroll
    for (int i = 0; i < 4; i++)
        out[(rowb + grp * 4 + i) * 128 + col] = acc4[i];
}

extern "C" void kernel_launch(void* const* d_in, const int* in_sizes, int n_in,
                              void* d_out, int out_size)
{
    const float* targets = (const float*)d_in[0];
    const float* hist    = (const float*)d_in[1];
    const float* Ww  = (const float*)d_in[2];  const float* Wb  = (const float*)d_in[3];
    const float* xuw = (const float*)d_in[4];  const float* xub = (const float*)d_in[5];
    const float* huw = (const float*)d_in[6];  const float* hub = (const float*)d_in[7];
    const float* xrw = (const float*)d_in[8];  const float* xrb = (const float*)d_in[9];
    const float* hrw = (const float*)d_in[10]; const float* hrb = (const float*)d_in[11];
    const float* xgw = (const float*)d_in[12]; const float* xgb = (const float*)d_in[13];
    const float* hgw = (const float*)d_in[14]; const float* hgb = (const float*)d_in[15];
    const float* lnw = (const float*)d_in[16]; const float* lnb = (const float*)d_in[17];
    float* out = (float*)d_out;

    cudaFuncSetAttribute(k1_ff, cudaFuncAttributeMaxDynamicSharedMemorySize, K1_SMEM);

    k0_dummy<<<1, 32>>>();
    k1_ff<<<148, 512, K1_SMEM>>>(targets, hist, Ww, Wb, xuw, xub, xrw, xrb, xgw, xgb);
    k2_softmax<<<1024, 256>>>();
    k3_scan<<<128, 256>>>(targets, huw, hub, hrw, hrb, hgw, hgb, lnw, lnb, out);
}

// round 16
// speedup vs baseline: 1.5450x; 1.3969x over previous
#include <cuda_runtime.h>
#include <cuda_fp16.h>
#include <cstdint>

// B=1024, T=200, IN=H=128. rows = 204800.
__device__ __half g_xall16[(size_t)204800 * 384];   // [flat row][xu|xr|xg] fp16, biases folded
__device__ float g_logits[204800];

__device__ __forceinline__ uint32_t smem_u32(const void* p) {
    return (uint32_t)__cvta_generic_to_shared(p);
}
__device__ __forceinline__ void ldmatrix_x4(uint32_t a[4], uint32_t addr) {
    asm volatile("ldmatrix.sync.aligned.m8n8.x4.shared.b16 {%0,%1,%2,%3}, [%4];"
                 : "=r"(a[0]), "=r"(a[1]), "=r"(a[2]), "=r"(a[3]) : "r"(addr));
}
__device__ __forceinline__ void ldmatrix_x4_trans(uint32_t a[4], uint32_t addr) {
    asm volatile("ldmatrix.sync.aligned.m8n8.x4.trans.shared.b16 {%0,%1,%2,%3}, [%4];"
                 : "=r"(a[0]), "=r"(a[1]), "=r"(a[2]), "=r"(a[3]) : "r"(addr));
}
__device__ __forceinline__ void mma16816(float c[4], const uint32_t a[4], uint32_t b0, uint32_t b1) {
    asm volatile("mma.sync.aligned.m16n8k16.row.col.f32.f16.f16.f32 "
                 "{%0,%1,%2,%3},{%4,%5,%6,%7},{%8,%9},{%0,%1,%2,%3};"
                 : "+f"(c[0]), "+f"(c[1]), "+f"(c[2]), "+f"(c[3])
                 : "r"(a[0]), "r"(a[1]), "r"(a[2]), "r"(a[3]), "r"(b0), "r"(b1));
}
__device__ __forceinline__ uint32_t f2h2(float x, float y) {
    __half2 h = __floats2half2_rn(x, y);
    return *reinterpret_cast<uint32_t*>(&h);
}
__device__ __forceinline__ float tanhapx(float x) {
    float y; asm("tanh.approx.f32 %0, %1;" : "=f"(y) : "f"(x)); return y;
}
__device__ __forceinline__ void cp_async16(uint32_t dst, const void* src) {
    asm volatile("cp.async.cg.shared.global [%0], [%1], 16;" :: "r"(dst), "l"(src));
}
__device__ __forceinline__ void cp_commit() { asm volatile("cp.async.commit_group;"); }
__device__ __forceinline__ void cp_wait0()  { asm volatile("cp.async.wait_group 0;" ::: "memory"); }
__device__ __forceinline__ void cp_wait1()  { asm volatile("cp.async.wait_group 1;" ::: "memory"); }

// ================= K0: dummies (keep ncu capture on k3_scan = 4th launch) =================
__global__ void k0_dummy() {}

// ================= K1: logits + x projections, cp.async input pipeline (frozen) =================
#define K1_RAWH_OFF 32768
#define K1_TG_OFF   65536
#define K1_HS_OFF   82944
#define K1_SWB_OFF  100352
#define K1_LGP_OFF  115712
#define K1_SMEM     116736
#define K1_TILES    3200

__global__ __launch_bounds__(512) void k1_ff(
    const float* __restrict__ targets, const float* __restrict__ hist,
    const float* __restrict__ Ww,  const float* __restrict__ Wb,
    const float* __restrict__ xuw, const float* __restrict__ xub,
    const float* __restrict__ xrw, const float* __restrict__ xrb,
    const float* __restrict__ xgw, const float* __restrict__ xgb)
{
    extern __shared__ char sm[];
    float4* rawT = (float4*)sm;
    float4* rawH = (float4*)(sm + K1_RAWH_OFF);
    __half* tg16 = (__half*)(sm + K1_TG_OFF);
    __half* hs16 = (__half*)(sm + K1_HS_OFF);
    uint32_t* swb = (uint32_t*)(sm + K1_SWB_OFF);
    float* lgp = (float*)(sm + K1_LGP_OFF);

    const int t = threadIdx.x, w = t >> 5, lane = t & 31;
    const int q = lane & 3, l4 = lane >> 2;
    const int g = w >> 2;
    const int cb = 32 * (w & 3);
    const bool is_logit = (g == 0);

    const float* W  = (g == 0) ? Ww  : (g == 1) ? xuw : (g == 2) ? xrw : xgw;
    const float* Bv = (g == 0) ? Wb  : (g == 1) ? xub : (g == 2) ? xrb : xgb;

    uint32_t bfr[4][8][2];
    float2 bs[4];
    #pragma unroll
    for (int ct = 0; ct < 4; ct++) {
        const int n = cb + 8 * ct + l4;
        bs[ct] = *(const float2*)&Bv[cb + 8 * ct + 2 * q];
        #pragma unroll
        for (int kt = 0; kt < 8; kt++) {
            float2 wa = *(const float2*)&W[n * 128 + kt * 16 + 2 * q];
            float2 wb = *(const float2*)&W[n * 128 + kt * 16 + 2 * q + 8];
            bfr[ct][kt][0] = f2h2(wa.x, wa.y);
            bfr[ct][kt][1] = f2h2(wb.x, wb.y);
        }
    }

    const uint32_t rawTu = smem_u32(rawT), rawHu = smem_u32(rawH);
    const uint32_t abase = smem_u32(is_logit ? tg16 : hs16)
                         + (lane & 15) * 272 + (lane >> 4) * 16;
    uint32_t* swbw = swb + (w - 4) * 320;
    const int gc0 = (g - 1) * 128 + cb;

    {
        const size_t base = (size_t)blockIdx.x * 64 * 128;
        #pragma unroll
        for (int j = 0; j < 4; j++) {
            int i = t + 512 * j;
            cp_async16(rawTu + 16 * i, &targets[base + 4 * i]);
            cp_async16(rawHu + 16 * i, &hist[base + 4 * i]);
        }
        cp_commit();
    }

    for (int tile = blockIdx.x; tile < K1_TILES; tile += 148) {
        const size_t row0 = (size_t)tile * 64;
        cp_wait0();
        __syncthreads();

        #pragma unroll
        for (int j = 0; j < 4; j++) {
            int i = t + 512 * j;
            int r = i >> 5, c = (i & 31) * 4;
            float4 v = rawT[i];
            uint2 p; p.x = f2h2(v.x, v.y); p.y = f2h2(v.z, v.w);
            *(uint2*)&tg16[r * 136 + c] = p;
            v = rawH[i];
            p.x = f2h2(v.x, v.y); p.y = f2h2(v.z, v.w);
            *(uint2*)&hs16[r * 136 + c] = p;
        }
        __syncthreads();

        if (tile + 148 < K1_TILES) {
            const size_t nbase = (size_t)(tile + 148) * 64 * 128;
            #pragma unroll
            for (int j = 0; j < 4; j++) {
                int i = t + 512 * j;
                cp_async16(rawTu + 16 * i, &targets[nbase + 4 * i]);
                cp_async16(rawHu + 16 * i, &hist[nbase + 4 * i]);
            }
        }
        cp_commit();

        #pragma unroll
        for (int mt = 0; mt < 4; mt++) {
            float acc[4][4];
            #pragma unroll
            for (int ct = 0; ct < 4; ct++) {
                if (is_logit) {
                    acc[ct][0] = acc[ct][1] = acc[ct][2] = acc[ct][3] = 0.f;
                } else {
                    acc[ct][0] = bs[ct].x; acc[ct][1] = bs[ct].y;
                    acc[ct][2] = bs[ct].x; acc[ct][3] = bs[ct].y;
                }
            }
            const uint32_t ab = abase + mt * 4352;
            #pragma unroll
            for (int kc = 0; kc < 2; kc++) {
                uint32_t af[4][4];
                #pragma unroll
                for (int k4 = 0; k4 < 4; k4++)
                    ldmatrix_x4(af[k4], ab + (4 * kc + k4) * 32);
                #pragma unroll
                for (int ct = 0; ct < 4; ct++)
                    #pragma unroll
                    for (int k4 = 0; k4 < 4; k4++)
                        mma16816(acc[ct], af[k4], bfr[ct][4 * kc + k4][0], bfr[ct][4 * kc + k4][1]);
            }
            const int r0 = mt * 16 + l4, r1 = r0 + 8;
            if (is_logit) {
                float p0 = 0.f, p1 = 0.f;
                #pragma unroll
                for (int ct = 0; ct < 4; ct++) {
                    const int col = cb + 8 * ct + 2 * q;
                    float2 h0 = __half22float2(*(const __half2*)&hs16[r0 * 136 + col]);
                    float2 h1 = __half22float2(*(const __half2*)&hs16[r1 * 136 + col]);
                    p0 += (acc[ct][0] + bs[ct].x) * h0.x + (acc[ct][1] + bs[ct].y) * h0.y;
                    p1 += (acc[ct][2] + bs[ct].x) * h1.x + (acc[ct][3] + bs[ct].y) * h1.y;
                }
                p0 += __shfl_xor_sync(~0u, p0, 1); p0 += __shfl_xor_sync(~0u, p0, 2);
                p1 += __shfl_xor_sync(~0u, p1, 1); p1 += __shfl_xor_sync(~0u, p1, 2);
                if (q == 0) {
                    lgp[w * 64 + r0] = p0;
                    lgp[w * 64 + r1] = p1;
                }
            } else {
                #pragma unroll
                for (int ct = 0; ct < 4; ct++) {
                    swbw[l4 * 20 + ct * 4 + q]       = f2h2(acc[ct][0], acc[ct][1]);
                    swbw[(l4 + 8) * 20 + ct * 4 + q] = f2h2(acc[ct][2], acc[ct][3]);
                }
                __syncwarp();
                #pragma unroll
                for (int i = lane; i < 256; i += 32) {
                    int row = i >> 4, c = i & 15;
                    uint32_t v = swbw[row * 20 + c];
                    *(uint32_t*)&g_xall16[(row0 + mt * 16 + row) * 384 + gc0 + 2 * c] = v;
                }
                __syncwarp();
            }
        }
        __syncthreads();
        if (t < 64)
            g_logits[row0 + t] = lgp[t] + lgp[64 + t] + lgp[128 + t] + lgp[192 + t];
    }
}

// ================= K3: GRU scan — cp.async x-feed (3-ring), fused softmax + final linear =================
#define XPAD 196                    // uint32 row stride (784 B)
#define XBUFB (8 * 784)             // bytes per x buffer = 6272

__global__ __launch_bounds__(256) void k3_scan(
    const float* __restrict__ targets,
    const float* __restrict__ huw, const float* __restrict__ hub,
    const float* __restrict__ hrw, const float* __restrict__ hrb,
    const float* __restrict__ hgw, const float* __restrict__ hgb,
    const float* __restrict__ lnw, const float* __restrict__ lnb,
    float* __restrict__ out)
{
    __shared__ __align__(16) __half hT[2][128 * 8];
    __shared__ __align__(16) uint32_t xbuf[3][8 * XPAD];
    __shared__ __align__(16) float attall[8][200];
    __shared__ __align__(16) float xs[8][260];
    const int t = threadIdx.x, w = t >> 5, lane = t & 31;
    const int q = lane & 3, l4 = lane >> 2;
    const size_t rowb = (size_t)blockIdx.x * 8;

    // ---- weight A-fragments (registers, once) ----
    uint32_t afr[3][8][4];
    float bias_[3][2];
    #pragma unroll
    for (int g = 0; g < 3; g++) {
        const float* W  = (g == 0) ? huw : (g == 1) ? hrw : hgw;
        const float* Bv = (g == 0) ? hub : (g == 1) ? hrb : hgb;
        bias_[g][0] = Bv[16 * w + l4];
        bias_[g][1] = Bv[16 * w + l4 + 8];
        #pragma unroll
        for (int kt = 0; kt < 8; kt++) {
            const float* bp = W + (16 * w + l4) * 128 + kt * 16 + 2 * q;
            float2 v0 = *(const float2*)(bp);
            float2 v2 = *(const float2*)(bp + 8);
            float2 v1 = *(const float2*)(bp + 8 * 128);
            float2 v3 = *(const float2*)(bp + 8 * 128 + 8);
            afr[g][kt][0] = f2h2(v0.x, v0.y);
            afr[g][kt][1] = f2h2(v1.x, v1.y);
            afr[g][kt][2] = f2h2(v2.x, v2.y);
            afr[g][kt][3] = f2h2(v3.x, v3.y);
        }
    }
    for (int i = t; i < 2048; i += 256) ((__half*)hT)[i] = __float2half(0.f);

    // ---- fused softmax (k2): warp w handles batch row rowb+w ----
    {
        const float* lg = &g_logits[(rowb + w) * 200];
        float mx = -1e30f;
        for (int i = lane; i < 200; i += 32) mx = fmaxf(mx, lg[i]);
        #pragma unroll
        for (int o = 16; o; o >>= 1) mx = fmaxf(mx, __shfl_xor_sync(~0u, mx, o));
        float s = 0.f;
        for (int i = lane; i < 200; i += 32) {
            float e = __expf(lg[i] - mx);
            attall[w][i] = e;
            s += e;
        }
        #pragma unroll
        for (int o = 16; o; o >>= 1) s += __shfl_xor_sync(~0u, s, o);
        float inv = __fdividef(1.f, s);
        for (int i = lane; i < 200; i += 32) attall[w][i] *= inv;
    }

    // ---- cp.async x-feed: per-thread chunk mapping (384 x 16B chunks/step) ----
    const int c0 = t, c1 = t + 256;
    const bool has1 = (c1 < 384);
    const int r0c = c0 / 48, o0 = c0 % 48;
    const int r1c = c1 / 48, o1 = c1 % 48;
    const char* src0 = (const char*)g_xall16 + ((rowb + r0c) * 200) * 768 + o0 * 16;
    const char* src1 = (const char*)g_xall16 + ((rowb + r1c) * 200) * 768 + o1 * 16;
    const uint32_t xbu = smem_u32(xbuf);
    const uint32_t dst0 = xbu + r0c * 784 + o0 * 16;
    const uint32_t dst1 = xbu + r1c * 784 + o1 * 16;

    // prologue: groups for step 0 (buf 0) and step 1 (buf 1)
    cp_async16(dst0, src0);
    if (has1) cp_async16(dst1, src1);
    cp_commit();
    cp_async16(dst0 + XBUFB, src0 + 768);
    if (has1) cp_async16(dst1 + XBUFB, src1 + 768);
    cp_commit();
    src0 += 2 * 768; src1 += 2 * 768;
    cp_wait1();                      // step-0 buffer landed
    __syncthreads();

    float hm[4] = {0.f, 0.f, 0.f, 0.f};
    const uint32_t hTb = smem_u32(hT) + lane * 16;
    const int colA = 16 * w + l4, colB = colA + 8;
    int buf = 0, buf2 = 2;           // buf = step%3, buf2 = (step+2)%3

    for (int step = 0; step < 200; step++) {
        const int rb = step & 1, wb = 1 - rb;

        // issue cp.async for step+2 (empty group near the end keeps counts aligned)
        if (step < 198) {
            cp_async16(dst0 + buf2 * XBUFB, src0);
            if (has1) cp_async16(dst1 + buf2 * XBUFB, src1);
            src0 += 768; src1 += 768;
        }
        cp_commit();

        // B-frags from hT
        uint32_t bf[8][2];
        #pragma unroll
        for (int j = 0; j < 4; j++) {
            uint32_t r4[4];
            ldmatrix_x4_trans(r4, hTb + rb * 2048 + j * 512);
            bf[2 * j][0] = r4[0]; bf[2 * j][1] = r4[1];
            bf[2 * j + 1][0] = r4[2]; bf[2 * j + 1][1] = r4[3];
        }
        // 6 interleaved mma chains, depth 4, zero-init
        float aA[3][4] = {{0,0,0,0},{0,0,0,0},{0,0,0,0}};
        float aB[3][4] = {{0,0,0,0},{0,0,0,0},{0,0,0,0}};
        #pragma unroll
        for (int k4 = 0; k4 < 4; k4++) {
            mma16816(aA[0], afr[0][k4],     bf[k4][0],     bf[k4][1]);
            mma16816(aB[0], afr[0][k4 + 4], bf[k4 + 4][0], bf[k4 + 4][1]);
            mma16816(aA[1], afr[1][k4],     bf[k4][0],     bf[k4][1]);
            mma16816(aB[1], afr[1][k4 + 4], bf[k4 + 4][0], bf[k4 + 4][1]);
            mma16816(aA[2], afr[2][k4],     bf[k4][0],     bf[k4][1]);
            mma16816(aB[2], afr[2][k4 + 4], bf[k4 + 4][0], bf[k4 + 4][1]);
        }

        // x-gather from smem ring (independent, overlaps mma)
        const char* xb = (const char*)xbuf + buf * XBUFB;
        float xu4[4], xr4[4], xg4[4];
        #pragma unroll
        for (int c = 0; c < 4; c++) {
            const int bofs = (2 * q + (c & 1)) * 784 + ((c >> 1) ? colB : colA) * 2;
            xu4[c] = __half2float(*(const __half*)(xb + bofs));
            xr4[c] = __half2float(*(const __half*)(xb + bofs + 256));
            xg4[c] = __half2float(*(const __half*)(xb + bofs + 512));
        }
        const float attv0 = attall[2 * q][step], attv1 = attall[2 * q + 1][step];

        float hn[4];
        #pragma unroll
        for (int c = 0; c < 4; c++) {
            const int hi = c >> 1;
            const float ae = (c & 1) ? attv1 : attv0;
            float su = aA[0][c] + aB[0][c] + xu4[c] + bias_[0][hi];
            float sr = aA[1][c] + aB[1][c] + xr4[c] + bias_[1][hi];
            float sg = aA[2][c] + aB[2][c] + bias_[2][hi];
            float u = fmaf(tanhapx(0.5f * su), 0.5f, 0.5f) * ae;
            float r = fmaf(tanhapx(0.5f * sr), 0.5f, 0.5f);
            float gg = tanhapx(fmaf(r, sg, xg4[c]));
            hn[c] = fmaf(u, gg - hm[c], hm[c]);
        }
        *(uint32_t*)((char*)hT[wb] + colA * 16 + 4 * q) = f2h2(hn[0], hn[1]);
        *(uint32_t*)((char*)hT[wb] + colB * 16 + 4 * q) = f2h2(hn[2], hn[3]);
        hm[0] = hn[0]; hm[1] = hn[1]; hm[2] = hn[2]; hm[3] = hn[3];

        cp_wait1();                  // next step's x buffer landed (issued 2 steps ago)
        __syncthreads();

        buf = (buf == 2) ? 0 : buf + 1;
        buf2 = (buf2 == 2) ? 0 : buf2 + 1;
    }

    // ---- fused final linear: out = [h, targets[:,0]] @ ln2_w^T + b ----
    xs[2 * q][colA]     = hm[0];
    xs[2 * q + 1][colA] = hm[1];
    xs[2 * q][colB]     = hm[2];
    xs[2 * q + 1][colB] = hm[3];
    for (int i = t; i < 1024; i += 256) {
        int bb = i >> 7, c = i & 127;
        xs[bb][128 + c] = targets[(size_t)(rowb + bb) * 200 * 128 + c];
    }
    __syncthreads();
    const int col = t & 127, grp = t >> 7;
    float acc4[4];
    const float bv = lnb[col];
    #pragma unroll
    for (int i = 0; i < 4; i++) acc4[i] = bv;
    const float4* wr = (const float4*)(lnw + (size_t)col * 256);
    #pragma unroll 4
    for (int k = 0; k < 64; k++) {
        float4 wv = wr[k];
        #pragma unroll
        for (int i = 0; i < 4; i++) {
            float4 xv = *(const float4*)&xs[grp * 4 + i][k * 4];
            acc4[i] += wv.x * xv.x + wv.y * xv.y + wv.z * xv.z + wv.w * xv.w;
        }
    }
    #pragma unroll
    for (int i = 0; i < 4; i++)
        out[(rowb + grp * 4 + i) * 128 + col] = acc4[i];
}

extern "C" void kernel_launch(void* const* d_in, const int* in_sizes, int n_in,
                              void* d_out, int out_size)
{
    const float* targets = (const float*)d_in[0];
    const float* hist    = (const float*)d_in[1];
    const float* Ww  = (const float*)d_in[2];  const float* Wb  = (const float*)d_in[3];
    const float* xuw = (const float*)d_in[4];  const float* xub = (const float*)d_in[5];
    const float* huw = (const float*)d_in[6];  const float* hub = (const float*)d_in[7];
    const float* xrw = (const float*)d_in[8];  const float* xrb = (const float*)d_in[9];
    const float* hrw = (const float*)d_in[10]; const float* hrb = (const float*)d_in[11];
    const float* xgw = (const float*)d_in[12]; const float* xgb = (const float*)d_in[13];
    const float* hgw = (const float*)d_in[14]; const float* hgb = (const float*)d_in[15];
    const float* lnw = (const float*)d_in[16]; const float* lnb = (const float*)d_in[17];
    float* out = (float*)d_out;

    cudaFuncSetAttribute(k1_ff, cudaFuncAttributeMaxDynamicSharedMemorySize, K1_SMEM);

    k0_dummy<<<1, 32>>>();
    k0_dummy<<<1, 32>>>();
    k1_ff<<<148, 512, K1_SMEM>>>(targets, hist, Ww, Wb, xuw, xub, xrw, xrb, xgw, xgb);
    k3_scan<<<128, 256>>>(targets, huw, hub, hrw, hrb, hgw, hgb, lnw, lnb, out);
}